// round 1
// baseline (speedup 1.0000x reference)
#include <cuda_runtime.h>
#include <math.h>

// ---------------------------------------------------------------------------
// QRNN: h_t = tanh(x_t @ Wh + b + h_{t-1} @ Uh),  T=512, B=32, D=1024
// Phase A: build Wh/Uh (1024x1024) from quaternion components
// Phase B: wh_out = x @ Wh + b  (one big fp32 SGEMM, written into d_out)
// Phase C: sequential recurrence, persistent kernel, flag-based sync,
//          deterministic fixed-order k-slice reduction (no float atomics)
// ---------------------------------------------------------------------------

#define TT 512
#define BB 32
#define DD 1024
#define QQ 256
#define NT 16      // n-tiles of width 64
#define KS 8       // k-slices of width 128
#define NTW 64
#define KSW 128

__device__ float g_Wh[DD * DD];                      // 4 MB
__device__ float g_Uh[DD * DD];                      // 4 MB
__device__ float g_partial[2][NT][KS][BB * NTW];     // 2 MB double-buffered partials
__device__ int   g_c1[TT][NT];                       // per (t, ntile) writer counter
__device__ int   g_done[TT][NT];                     // per (t, ntile) "h finalized" flag

// --------------------------- flag reset (per launch) -----------------------
__global__ void zero_flags_kernel() {
    int i = blockIdx.x * blockDim.x + threadIdx.x;
    if (i < TT * NT) {
        (&g_c1[0][0])[i]   = 0;
        (&g_done[0][0])[i] = 0;
    }
}

// --------------------------- quaternion matrix build -----------------------
// Block (br, bc): component index = br ^ bc; sign from per-row nibble mask
// masks: br0=0x0, br1=0x9, br2=0x3, br3=0x5  (bit bc set => negative)
__global__ void build_qmat_kernel(const float* __restrict__ wr,
                                  const float* __restrict__ wi,
                                  const float* __restrict__ wj,
                                  const float* __restrict__ wk,
                                  int which) {
    int e = blockIdx.x * blockDim.x + threadIdx.x;   // column 0..1023
    int d = blockIdx.y;                              // row    0..1023
    int br = d >> 8, bc = e >> 8;
    int r = d & 255, c = e & 255;
    int comp = br ^ bc;
    int mask = (0x5390 >> (br * 4)) & 0xF;
    float s = ((mask >> bc) & 1) ? -1.0f : 1.0f;
    const float* w = (comp == 0) ? wr : (comp == 1) ? wi : (comp == 2) ? wj : wk;
    float* W = which ? g_Uh : g_Wh;
    W[d * DD + e] = s * w[r * QQ + c];
}

// --------------------------- fp32 SGEMM (128x128x8, 8x8/thread) ------------
#define GBM 128
#define GBN 128
#define GBK 8

__global__ void __launch_bounds__(256)
sgemm_bias_kernel(const float* __restrict__ A, const float* __restrict__ bias,
                  float* __restrict__ C, int M, int N, int K) {
    __shared__ float As[2][GBK][GBM];
    __shared__ float Bs[2][GBK][GBN];
    const float* Bmat = g_Wh;

    int tid  = threadIdx.x;
    int brow = blockIdx.y, bcol = blockIdx.x;
    int arow = tid >> 1,  acol = (tid & 1) << 2;     // A tile load: 128x8
    int brl  = tid >> 5,  bcl  = (tid & 31) << 2;    // B tile load: 8x128

    const float* Ab = A + (size_t)(brow * GBM) * K;
    const float* Bb = Bmat + bcol * GBN;

    float4 av = *(const float4*)&Ab[(size_t)arow * K + acol];
    float4 bv = *(const float4*)&Bb[(size_t)brl * N + bcl];
    As[0][acol + 0][arow] = av.x;
    As[0][acol + 1][arow] = av.y;
    As[0][acol + 2][arow] = av.z;
    As[0][acol + 3][arow] = av.w;
    *(float4*)&Bs[0][brl][bcl] = bv;
    __syncthreads();

    int tm = (tid >> 4) << 3;
    int tn = (tid & 15) << 3;
    float acc[8][8];
#pragma unroll
    for (int i = 0; i < 8; i++)
#pragma unroll
        for (int j = 0; j < 8; j++) acc[i][j] = 0.0f;

    int nk = K / GBK;
    for (int kt = 0; kt < nk; ++kt) {
        int cur = kt & 1;
        float4 an, bn;
        if (kt + 1 < nk) {
            an = *(const float4*)&Ab[(size_t)arow * K + (kt + 1) * GBK + acol];
            bn = *(const float4*)&Bb[(size_t)((kt + 1) * GBK + brl) * N + bcl];
        }
#pragma unroll
        for (int kk = 0; kk < GBK; kk++) {
            float ra[8], rb[8];
            *(float4*)&ra[0] = *(const float4*)&As[cur][kk][tm];
            *(float4*)&ra[4] = *(const float4*)&As[cur][kk][tm + 4];
            *(float4*)&rb[0] = *(const float4*)&Bs[cur][kk][tn];
            *(float4*)&rb[4] = *(const float4*)&Bs[cur][kk][tn + 4];
#pragma unroll
            for (int i = 0; i < 8; i++)
#pragma unroll
                for (int j = 0; j < 8; j++) acc[i][j] += ra[i] * rb[j];
        }
        if (kt + 1 < nk) {
            int nxt = cur ^ 1;
            As[nxt][acol + 0][arow] = an.x;
            As[nxt][acol + 1][arow] = an.y;
            As[nxt][acol + 2][arow] = an.z;
            As[nxt][acol + 3][arow] = an.w;
            *(float4*)&Bs[nxt][brl][bcl] = bn;
            __syncthreads();
        }
    }

    float bias_r[8];
#pragma unroll
    for (int j = 0; j < 8; j++) bias_r[j] = bias[bcol * GBN + tn + j];
#pragma unroll
    for (int i = 0; i < 8; i++) {
        float4 v0 = make_float4(acc[i][0] + bias_r[0], acc[i][1] + bias_r[1],
                                acc[i][2] + bias_r[2], acc[i][3] + bias_r[3]);
        float4 v1 = make_float4(acc[i][4] + bias_r[4], acc[i][5] + bias_r[5],
                                acc[i][6] + bias_r[6], acc[i][7] + bias_r[7]);
        size_t row = (size_t)(brow * GBM + tm + i) * N + bcol * GBN + tn;
        *(float4*)&C[row]     = v0;
        *(float4*)&C[row + 4] = v1;
    }
}

// --------------------------- recurrence (persistent, flag-synced) ----------
// 128 CTAs = 16 n-tiles x 8 k-slices. Each CTA holds Uh[kslice, ntile] in SMEM.
// Per step: stage h[t-1][:, kslice] -> smem, 32x64x128 partial GEMM ->
// partial buffer (parity t&1), bump counter; one fixed finalizer CTA per
// n-tile sums 8 partials in fixed order + wh, applies tanh, sets done flag.
__global__ void __launch_bounds__(128)
recur_kernel(float* __restrict__ out) {
    int n   = blockIdx.x >> 3;
    int k   = blockIdx.x & 7;
    int tid = threadIdx.x;

    __shared__ float Us[KSW][NTW];   // 32 KB: Uh[k*128+kk][n*64+c]
    __shared__ float hs[KSW][36];    // h slice staged transposed: hs[kk][b]

    for (int i = tid; i < KSW * NTW; i += 128) {
        int kk = i >> 6, c = i & 63;
        Us[kk][c] = g_Uh[(size_t)(k * KSW + kk) * DD + n * NTW + c];
    }

    // t = 0: h0 = tanh(wh_out[0]); finalized by the k==0 CTA of each n-tile
    if (k == 0) {
        for (int i = tid; i < BB * NTW; i += 128) {
            int b = i >> 6, c = i & 63;
            size_t idx = (size_t)b * DD + n * NTW + c;
            out[idx] = tanhf(out[idx]);
        }
        __threadfence();
        __syncthreads();
        if (tid == 0) atomicExch(&g_done[0][n], 1);
    }

    int b0 = (tid >> 4) << 2;        // 8 groups of 4 batch rows
    int c0 = (tid & 15) << 2;        // 16 groups of 4 columns
    bool is_fin = (k == (n & 7));

    for (int t = 1; t < TT; ++t) {
        if (tid == 0) {
            // h[t-1] columns this CTA reads = ntiles 2k, 2k+1
            while (atomicAdd(&g_done[t - 1][2 * k], 0) == 0) {}
            while (atomicAdd(&g_done[t - 1][2 * k + 1], 0) == 0) {}
            // own-ntile finalizer of t-1 done => partial buffer (t&1) reusable
            while (atomicAdd(&g_done[t - 1][n], 0) == 0) {}
        }
        __syncthreads();

        // stage h[t-1][b][k*128 + kk] into hs[kk][b]  (coalesced global reads)
        const float* hrow = out + (size_t)(t - 1) * BB * DD + k * KSW;
#pragma unroll
        for (int i = 0; i < BB; ++i)
            hs[tid][i] = __ldcg(&hrow[(size_t)i * DD + tid]);
        __syncthreads();

        float acc[4][4];
#pragma unroll
        for (int i = 0; i < 4; i++)
#pragma unroll
            for (int j = 0; j < 4; j++) acc[i][j] = 0.0f;

#pragma unroll 8
        for (int kk = 0; kk < KSW; ++kk) {
            float4 hv = *(const float4*)&hs[kk][b0];
            float4 uv = *(const float4*)&Us[kk][c0];
            float ha[4] = {hv.x, hv.y, hv.z, hv.w};
            float ua[4] = {uv.x, uv.y, uv.z, uv.w};
#pragma unroll
            for (int i = 0; i < 4; i++)
#pragma unroll
                for (int j = 0; j < 4; j++) acc[i][j] += ha[i] * ua[j];
        }

        float* pb = &g_partial[t & 1][n][k][0];
#pragma unroll
        for (int i = 0; i < 4; i++) {
            float4 v = make_float4(acc[i][0], acc[i][1], acc[i][2], acc[i][3]);
            *(float4*)&pb[(b0 + i) * NTW + c0] = v;
        }
        __threadfence();
        __syncthreads();
        if (tid == 0) atomicAdd(&g_c1[t][n], 1);

        if (is_fin) {
            if (tid == 0) {
                while (atomicAdd(&g_c1[t][n], 0) < KS) {}
            }
            __syncthreads();
            float* orow = out + (size_t)t * BB * DD + n * NTW;
            for (int i = tid; i < BB * NTW; i += 128) {
                int b = i >> 6, c = i & 63;
                float s = __ldcg(&orow[(size_t)b * DD + c]);   // wh_out value
#pragma unroll
                for (int q = 0; q < KS; ++q)
                    s += __ldcg(&g_partial[t & 1][n][q][b * NTW + c]);
                orow[(size_t)b * DD + c] = tanhf(s);
            }
            __threadfence();
            __syncthreads();
            if (tid == 0) atomicExch(&g_done[t][n], 1);
        }
    }
}

// --------------------------- launch ----------------------------------------
extern "C" void kernel_launch(void* const* d_in, const int* in_sizes, int n_in,
                              void* d_out, int out_size) {
    const float* x    = (const float*)d_in[0];
    const float* wh_r = (const float*)d_in[1];
    const float* wh_i = (const float*)d_in[2];
    const float* wh_j = (const float*)d_in[3];
    const float* wh_k = (const float*)d_in[4];
    const float* uh_r = (const float*)d_in[5];
    const float* uh_i = (const float*)d_in[6];
    const float* uh_j = (const float*)d_in[7];
    const float* uh_k = (const float*)d_in[8];
    const float* wh_b = (const float*)d_in[9];
    float* out = (float*)d_out;

    zero_flags_kernel<<<(TT * NT + 255) / 256, 256>>>();

    dim3 bq(DD / 256, DD);
    build_qmat_kernel<<<bq, 256>>>(wh_r, wh_i, wh_j, wh_k, 0);
    build_qmat_kernel<<<bq, 256>>>(uh_r, uh_i, uh_j, uh_k, 1);

    dim3 gg(DD / GBN, (TT * BB) / GBM);   // (8, 128)
    sgemm_bias_kernel<<<gg, 256>>>(x, wh_b, out, TT * BB, DD, DD);

    recur_kernel<<<NT * KS, 128>>>(out);
}